// round 5
// baseline (speedup 1.0000x reference)
#include <cuda_runtime.h>
#include <cuda_bf16.h>

#define NN 100000
#define EE 800000
#define DD 64
#define HH 4

// Scratch (device globals; no allocation allowed)
__device__ float g_Q[NN * DD];
__device__ float g_K[NN * DD];
__device__ float g_V[NN * DD];
__device__ int   g_cnt[NN];
__device__ int   g_off[NN + 1];
__device__ int   g_cur[NN];
__device__ int   g_bsum[128];
__device__ int   g_scol[EE];

// ---------------------------------------------------------------------------
// Packed f32x2 helpers (sm_103a): ptxas never auto-fuses these.
// ---------------------------------------------------------------------------
__device__ __forceinline__ unsigned long long ffma2(
    unsigned long long a, unsigned long long b, unsigned long long c)
{
    unsigned long long d;
    asm("fma.rn.f32x2 %0, %1, %2, %3;" : "=l"(d) : "l"(a), "l"(b), "l"(c));
    return d;
}

__device__ __forceinline__ float unpack_sum(unsigned long long a)
{
    float lo, hi;
    asm("mov.b64 {%0, %1}, %2;" : "=f"(lo), "=f"(hi) : "l"(a));
    return lo + hi;
}

__device__ __forceinline__ unsigned long long pack2(float lo, float hi)
{
    unsigned long long u;
    asm("mov.b64 %0, {%1, %2};" : "=l"(u) : "f"(lo), "f"(hi));
    return u;
}

// ---------------------------------------------------------------------------
// 1) Node projections with f32x2-packed FMAs, paired over k.
//    sW[m][kp][d] = {W[2kp][d], W[2kp+1][d]}  (48 KB shared, pre-swizzled).
//    Weights read as LDS.128 (2 packed pairs per load) to halve LDS issues.
// ---------------------------------------------------------------------------
__global__ __launch_bounds__(128) void proj_kernel(
    const float* __restrict__ X,
    const float* __restrict__ Wq,
    const float* __restrict__ Wk,
    const float* __restrict__ Wv)
{
    __shared__ unsigned long long sW[3][DD / 2][DD];   // 3*32*64*8 = 48 KB

    // Stage + k-pair-swizzle the weights (coalesced in d).
    for (int i = threadIdx.x; i < 3 * (DD / 2) * DD; i += 128) {
        int m  = i / ((DD / 2) * DD);
        int r  = i % ((DD / 2) * DD);
        int kp = r / DD;
        int d  = r % DD;
        const float* W = (m == 0) ? Wq : (m == 1) ? Wk : Wv;
        sW[m][kp][d] = pack2(W[(2 * kp) * DD + d], W[(2 * kp + 1) * DD + d]);
    }
    __syncthreads();

    int node = blockIdx.x * 128 + threadIdx.x;
    if (node >= NN) return;

    // Load x row as 16x 16B -> 32 packed ulls {x[2k], x[2k+1]}
    unsigned long long xp[DD / 2];
    const ulonglong2* xr = (const ulonglong2*)(X + (size_t)node * DD);
#pragma unroll
    for (int i = 0; i < DD / 8 * 2; i++) {
        ulonglong2 t = xr[i];
        xp[2 * i]     = t.x;
        xp[2 * i + 1] = t.y;
    }

    float* outs[3] = { g_Q + (size_t)node * DD,
                       g_K + (size_t)node * DD,
                       g_V + (size_t)node * DD };

#pragma unroll 1
    for (int m = 0; m < 3; m++) {
        float* out = outs[m];
#pragma unroll 1
        for (int dc = 0; dc < DD; dc += 8) {
            unsigned long long a0 = 0, a1 = 0, a2 = 0, a3 = 0,
                               a4 = 0, a5 = 0, a6 = 0, a7 = 0;
#pragma unroll
            for (int kp = 0; kp < DD / 2; kp++) {
                const ulonglong2* w2 = (const ulonglong2*)&sW[m][kp][dc];
                unsigned long long x2 = xp[kp];
                ulonglong2 wa = w2[0];
                ulonglong2 wb = w2[1];
                ulonglong2 wc = w2[2];
                ulonglong2 wd = w2[3];
                a0 = ffma2(x2, wa.x, a0);
                a1 = ffma2(x2, wa.y, a1);
                a2 = ffma2(x2, wb.x, a2);
                a3 = ffma2(x2, wb.y, a3);
                a4 = ffma2(x2, wc.x, a4);
                a5 = ffma2(x2, wc.y, a5);
                a6 = ffma2(x2, wd.x, a6);
                a7 = ffma2(x2, wd.y, a7);
            }
            float4 o0 = make_float4(unpack_sum(a0), unpack_sum(a1),
                                    unpack_sum(a2), unpack_sum(a3));
            float4 o1 = make_float4(unpack_sum(a4), unpack_sum(a5),
                                    unpack_sum(a6), unpack_sum(a7));
            *(float4*)(out + dc)     = o0;
            *(float4*)(out + dc + 4) = o1;
        }
    }
}

// ---------------------------------------------------------------------------
// 2) CSR build: zero counts -> histogram -> warp-shuffle scan -> scan sums ->
//    add offsets (+cursor init) -> scatter cols sorted by destination row.
// ---------------------------------------------------------------------------
__global__ void zero_cnt_kernel()
{
    int i = blockIdx.x * blockDim.x + threadIdx.x;
    if (i < NN) g_cnt[i] = 0;
}

__global__ void hist_kernel(const int* __restrict__ rows)
{
    int e = blockIdx.x * blockDim.x + threadIdx.x;
    if (e < EE) atomicAdd(&g_cnt[rows[e]], 1);
}

__global__ __launch_bounds__(1024) void scan_block_kernel()
{
    __shared__ int wsum[32];
    int i    = blockIdx.x * 1024 + threadIdx.x;
    int lane = threadIdx.x & 31;
    int w    = threadIdx.x >> 5;
    int v    = (i < NN) ? g_cnt[i] : 0;

    // warp inclusive scan
    int s = v;
#pragma unroll
    for (int o = 1; o < 32; o <<= 1) {
        int t = __shfl_up_sync(0xffffffffu, s, o);
        if (lane >= o) s += t;
    }
    if (lane == 31) wsum[w] = s;
    __syncthreads();

    if (w == 0) {
        int ws = wsum[lane];
        int t  = ws;
#pragma unroll
        for (int o = 1; o < 32; o <<= 1) {
            int u = __shfl_up_sync(0xffffffffu, t, o);
            if (lane >= o) t += u;
        }
        wsum[lane] = t - ws;   // exclusive warp prefix
    }
    __syncthreads();

    int incl = s + wsum[w];
    if (i < NN) g_off[i] = incl - v;                       // exclusive
    if (threadIdx.x == 1023) g_bsum[blockIdx.x] = incl;    // block total
}

__global__ void scan_sums_kernel(int nb)
{
    if (threadIdx.x == 0 && blockIdx.x == 0) {
        int acc = 0;
        for (int b = 0; b < nb; b++) { int t = g_bsum[b]; g_bsum[b] = acc; acc += t; }
    }
}

__global__ void add_off_kernel()
{
    int i = blockIdx.x * blockDim.x + threadIdx.x;
    if (i < NN) {
        int o = g_off[i] + g_bsum[i >> 10];
        g_off[i] = o;
        g_cur[i] = o;
    }
    if (i == 0) g_off[NN] = EE;
}

__global__ void scatter_kernel(const int* __restrict__ rows,
                               const int* __restrict__ cols)
{
    int e = blockIdx.x * blockDim.x + threadIdx.x;
    if (e < EE) {
        int p = atomicAdd(&g_cur[rows[e]], 1);
        g_scol[p] = cols[e];
    }
}

// ---------------------------------------------------------------------------
// 3) Fused attention aggregate: one warp per destination node.
//    8 lanes per edge, 4 edges in flight per warp.
//    lane = g*8 + sub: group g owns edge slot j+g; sub owns dims [8*sub,8*sub+8).
//    dh=16 => head h = sub/2; the two sub-lanes of a head are xor-1 partners,
//    so ONE shfl_xor(1) completes the per-head dot (vs a 3-deep tree).
//    K/V rows loaded as 2x LDG.128 per lane => one 128B line per edge per load.
// ---------------------------------------------------------------------------
__global__ __launch_bounds__(256) void aggregate_kernel(float* __restrict__ out)
{
    int warp = (blockIdx.x * blockDim.x + threadIdx.x) >> 5;
    int lane = threadIdx.x & 31;
    if (warp >= NN) return;

    int g   = lane >> 3;     // edge slot within 4-edge batch
    int sub = lane & 7;      // dim-octet owner

    int start = g_off[warp];
    int end   = g_off[warp + 1];

    // q: this lane's 8 dims (broadcast across the 4 groups)
    const float4* qp = (const float4*)(g_Q + (size_t)warp * DD + sub * 8);
    float4 qa = qp[0];
    float4 qb = qp[1];

    float acc[8] = {0.f, 0.f, 0.f, 0.f, 0.f, 0.f, 0.f, 0.f};
    float na = 0.f;

    // software-pipelined column index
    int c_next = (start + g < end) ? __ldg(&g_scol[start + g]) : 0;

    for (int j = start; j < end; j += 4) {
        int  c   = c_next;
        bool act = (j + g) < end;
        int  jn  = j + 4 + g;
        c_next = (jn < end) ? __ldg(&g_scol[jn]) : 0;

        const float4* kp = (const float4*)(g_K + (size_t)c * DD + sub * 8);
        const float4* vp = (const float4*)(g_V + (size_t)c * DD + sub * 8);
        float4 ka = kp[0];
        float4 kb = kp[1];
        float4 va = vp[0];
        float4 vb = vp[1];

        float p = qa.x * ka.x + qa.y * ka.y + qa.z * ka.z + qa.w * ka.w
                + qb.x * kb.x + qb.y * kb.y + qb.z * kb.z + qb.w * kb.w;
        p += __shfl_xor_sync(0xffffffffu, p, 1);   // head dot complete
        p = fminf(10.f, fmaxf(-10.f, p));
        float ea = act ? __expf(p) : 0.f;

        na += ea;
        acc[0] += ea * va.x; acc[1] += ea * va.y;
        acc[2] += ea * va.z; acc[3] += ea * va.w;
        acc[4] += ea * vb.x; acc[5] += ea * vb.y;
        acc[6] += ea * vb.z; acc[7] += ea * vb.w;
    }

    // combine the 4 edge groups (same sub/dims, disjoint edges)
#pragma unroll
    for (int o = 8; o < 32; o <<= 1) {
        na += __shfl_xor_sync(0xffffffffu, na, o);
#pragma unroll
        for (int i = 0; i < 8; i++)
            acc[i] += __shfl_xor_sync(0xffffffffu, acc[i], o);
    }

    if (g == 0) {
        float inv = 1.f / (na + 1e-8f);
        float4 o0 = make_float4(acc[0] * inv, acc[1] * inv,
                                acc[2] * inv, acc[3] * inv);
        float4 o1 = make_float4(acc[4] * inv, acc[5] * inv,
                                acc[6] * inv, acc[7] * inv);
        float4* op = (float4*)(out + (size_t)warp * DD + sub * 8);
        op[0] = o0;
        op[1] = o1;
    }
}

// ---------------------------------------------------------------------------
extern "C" void kernel_launch(void* const* d_in, const int* in_sizes, int n_in,
                              void* d_out, int out_size)
{
    const float* X  = (const float*)d_in[0];
    const float* Wq = (const float*)d_in[1];
    const float* Wk = (const float*)d_in[2];
    const float* Wv = (const float*)d_in[3];
    const int*   ei = (const int*)d_in[4];
    const int* rows = ei;
    const int* cols = ei + EE;
    float* out = (float*)d_out;

    (void)in_sizes; (void)n_in; (void)out_size;

    // 1) node projections
    proj_kernel<<<(NN + 127) / 128, 128>>>(X, Wq, Wk, Wv);

    // 2) CSR build by destination row
    zero_cnt_kernel<<<(NN + 255) / 256, 256>>>();
    hist_kernel<<<(EE + 255) / 256, 256>>>(rows);
    int nb = (NN + 1023) / 1024;
    scan_block_kernel<<<nb, 1024>>>();
    scan_sums_kernel<<<1, 32>>>(nb);
    add_off_kernel<<<(NN + 255) / 256, 256>>>();
    scatter_kernel<<<(EE + 255) / 256, 256>>>(rows, cols);

    // 3) fused gather + softmax + aggregate (one warp per node)
    aggregate_kernel<<<(NN * 32 + 255) / 256, 256>>>(out);
}